// round 7
// baseline (speedup 1.0000x reference)
#include <cuda_runtime.h>

#define NUM_NODES 100000
#define NUM_EDGES 6400000
#define NUM_STEPS 10

#define TILE 10000                 // dst nodes per tile (40KB smem acc)
#define NTILES 10                  // NUM_NODES / TILE
#define CTAS_PER_TILE 30           // 300 CTAs -> 2 CTAs/SM
#define STEP_TPB 1024

#define NBINS (NTILES * NUM_NODES) // 1,000,000 bins: key = dst_tile*N + src
#define SCAN_BLK 1024
#define NSB ((NBINS + SCAN_BLK - 1) / SCAN_BLK)   // 977

// Scratch (allocation-free rule: __device__ globals)
__device__ int2  g_edges[NUM_EDGES];      // {bin, packed src<<14|dst_local}
__device__ __align__(16) uint2 g_sp2[NUM_EDGES];  // {packed, prob-bits}, bin-sorted
__device__ int   g_bins[NBINS];
__device__ int   g_binptr[NBINS + 1];
__device__ int   g_cursor[NBINS];
__device__ int   g_blocksum[NSB];
__device__ float g_curA[NUM_NODES];
__device__ float g_curB[NUM_NODES];
__device__ float g_surv[NUM_NODES];
__device__ float g_acc[NUM_NODES];
__device__ int   g_is64;
__device__ int   g_ticket;

// ---------------------------------------------------------------------------
// Fused: detect int64-vs-int32 (block 0), zero bins, reset ticket, init nodes.
// ---------------------------------------------------------------------------
__global__ void prep_kernel(const int* __restrict__ w, const float* __restrict__ x) {
    int i = blockIdx.x * blockDim.x + threadIdx.x;
    if (blockIdx.x == 0) {
        __shared__ int nz;
        if (threadIdx.x == 0) { nz = 0; g_ticket = 0; }
        __syncthreads();
        for (int k = threadIdx.x; k < 4096; k += blockDim.x)
            if (w[2 * k + 1] != 0) nz = 1;
        __syncthreads();
        if (threadIdx.x == 0) g_is64 = nz ? 0 : 1;
    }
    if (i < NBINS) g_bins[i] = 0;
    if (i < NUM_NODES) {
        float xv = x[i];
        g_curA[i] = xv;
        g_surv[i] = 1.0f - xv;
        g_acc[i]  = 0.0f;
    }
}

// ---------------------------------------------------------------------------
// Convert edges -> {bin, packed} AND histogram bins.
// bin = dst_tile * NUM_NODES + src ; packed = src << 14 | dst_local
// ---------------------------------------------------------------------------
__global__ void convert_hist_kernel(const void* __restrict__ eidx) {
    int i = blockIdx.x * blockDim.x + threadIdx.x;
    if (i >= NUM_EDGES) return;
    int s, d;
    if (g_is64) {
        const long long* e = (const long long*)eidx;
        s = (int)e[i];
        d = (int)e[NUM_EDGES + i];
    } else {
        const int* e = (const int*)eidx;
        s = e[i];
        d = e[NUM_EDGES + i];
    }
    s = min(max(s, 0), NUM_NODES - 1);
    d = min(max(d, 0), NUM_NODES - 1);
    int tile = d / TILE;
    int dl   = d - tile * TILE;
    int bin  = tile * NUM_NODES + s;
    g_edges[i] = make_int2(bin, (s << 14) | dl);
    atomicAdd(&g_bins[bin], 1);
}

// ---------------------------------------------------------------------------
// Single-kernel exclusive scan: per-block scan + last-block (ticket) finalize.
// Produces final g_binptr AND g_cursor in one launch.
// ---------------------------------------------------------------------------
__global__ void scan_full_kernel() {
    __shared__ int s[SCAN_BLK];
    __shared__ int off[SCAN_BLK];
    __shared__ int is_last;
    int tid = threadIdx.x;
    int i = blockIdx.x * SCAN_BLK + tid;
    int v = (i < NBINS) ? g_bins[i] : 0;
    s[tid] = v;
    __syncthreads();
    #pragma unroll
    for (int o = 1; o < SCAN_BLK; o <<= 1) {
        int t = (tid >= o) ? s[tid - o] : 0;
        __syncthreads();
        s[tid] += t;
        __syncthreads();
    }
    if (i < NBINS) g_binptr[i] = s[tid] - v;        // exclusive, sans block offset
    if (tid == SCAN_BLK - 1) g_blocksum[blockIdx.x] = s[tid];

    // last block finalizes
    __threadfence();
    if (tid == 0) {
        int t = atomicAdd(&g_ticket, 1);
        is_last = (t == gridDim.x - 1) ? 1 : 0;
    }
    __syncthreads();
    if (!is_last) return;

    int bv = (tid < NSB) ? g_blocksum[tid] : 0;
    off[tid] = bv;
    __syncthreads();
    #pragma unroll
    for (int o = 1; o < SCAN_BLK; o <<= 1) {
        int t = (tid >= o) ? off[tid - o] : 0;
        __syncthreads();
        off[tid] += t;
        __syncthreads();
    }
    // off[tid] inclusive -> exclusive = off[tid] - bv
    off[tid] -= bv;
    __syncthreads();

    for (int k = tid; k < NBINS; k += SCAN_BLK) {
        int r = g_binptr[k] + off[k >> 10];
        g_binptr[k] = r;
        g_cursor[k] = r;
    }
    if (tid == 0) g_binptr[NBINS] = NUM_EDGES;
}

// ---------------------------------------------------------------------------
// Scatter into (dst_tile, src)-sorted order.
// ---------------------------------------------------------------------------
__global__ void scatter_kernel(const float* __restrict__ probs) {
    int i = blockIdx.x * blockDim.x + threadIdx.x;
    if (i >= NUM_EDGES) return;
    int2 e = g_edges[i];
    float p = probs[i];
    int pos = atomicAdd(&g_cursor[e.x], 1);
    g_sp2[pos] = make_uint2((unsigned)e.y, (unsigned)__float_as_int(p));
}

// ---------------------------------------------------------------------------
// Per-step edge pass: one dst tile per CTA group, smem accumulation.
// srcs ascend within a tile slice -> streaming gathers. 2-edge uint4 loads.
// ---------------------------------------------------------------------------
__device__ __forceinline__ void process_edge(unsigned k, unsigned p,
                                             const float* cur, float* acc) {
    int src = (int)(k >> 14);
    int dl  = (int)(k & 16383u);
    atomicAdd(&acc[dl], __ldg(&cur[src]) * __int_as_float((int)p));
}

__global__ void __launch_bounds__(STEP_TPB)
spmv_tile_kernel(int step) {
    __shared__ float acc[TILE];
    int tile = blockIdx.x / CTAS_PER_TILE;
    int sub  = blockIdx.x % CTAS_PER_TILE;

    for (int i = threadIdx.x; i < TILE; i += STEP_TPB) acc[i] = 0.0f;
    __syncthreads();

    const float* cur = (step & 1) ? g_curB : g_curA;

    int start = g_binptr[tile * NUM_NODES];
    int end   = g_binptr[(tile + 1) * NUM_NODES];
    int n = end - start;
    int per = (n + CTAS_PER_TILE - 1) / CTAS_PER_TILE;
    int a = start + sub * per;
    int b = min(a + per, end);
    if (a > b) a = b;

    // scalar head to reach 16B alignment (even index)
    if (a < b && (a & 1)) {
        if (threadIdx.x == 0) {
            uint2 e = g_sp2[a];
            process_edge(e.x, e.y, cur, acc);
        }
        a++;
    }

    for (int j = a + threadIdx.x * 2; j < b; j += STEP_TPB * 2) {
        if (j + 1 < b) {
            uint4 e2 = *reinterpret_cast<const uint4*>(&g_sp2[j]);
            process_edge(e2.x, e2.y, cur, acc);
            process_edge(e2.z, e2.w, cur, acc);
        } else {
            uint2 e = g_sp2[j];
            process_edge(e.x, e.y, cur, acc);
        }
    }
    __syncthreads();

    int base = tile * TILE;
    for (int i = threadIdx.x; i < TILE; i += STEP_TPB) {
        float v = acc[i];
        if (v != 0.0f) atomicAdd(&g_acc[base + i], v);
    }
}

// ---------------------------------------------------------------------------
// Per-step node pass: cur' = scale*acc + bias; surv *= (1-cur'); acc = 0.
// Buffer parity resolved in device code (host &symbol is invalid).
// ---------------------------------------------------------------------------
__global__ void node_kernel(const float* __restrict__ td,
                            const float* __restrict__ ew,
                            const float* __restrict__ nb,
                            int step, int is_last,
                            float* __restrict__ out) {
    int n = blockIdx.x * blockDim.x + threadIdx.x;
    if (n >= NUM_NODES) return;

    float* curn = (step & 1) ? g_curA : g_curB;

    float tdv = td[step];
    float scale = ew[step] * expf(-(tdv * tdv));
    float c = scale * g_acc[n] + nb[0];
    g_acc[n] = 0.0f;
    curn[n] = c;
    float sv = g_surv[n] * (1.0f - c);
    g_surv[n] = sv;
    if (is_last) {
        float fi = 1.0f - sv;
        out[n] = fminf(fmaxf(fi, 0.0f), 1.0f);
    }
}

// ---------------------------------------------------------------------------
// Launch
// ---------------------------------------------------------------------------
extern "C" void kernel_launch(void* const* d_in, const int* in_sizes, int n_in,
                              void* d_out, int out_size) {
    const float* x     = (const float*)d_in[0];
    const void*  eidx  = d_in[1];
    const float* probs = (const float*)d_in[2];
    const float* td    = (const float*)d_in[3];
    const float* nb    = (const float*)d_in[4];
    const float* ew    = (const float*)d_in[5];
    float*       out   = (float*)d_out;

    const int TB = 256;
    int eblocks = (NUM_EDGES + TB - 1) / TB;
    int nblocks = (NUM_NODES + TB - 1) / TB;
    int bblocks = (NBINS + TB - 1) / TB;

    prep_kernel<<<bblocks, TB>>>((const int*)eidx, x);        // launch 0
    convert_hist_kernel<<<eblocks, TB>>>(eidx);               // launch 1
    scan_full_kernel<<<NSB, SCAN_BLK>>>();                    // launch 2
    scatter_kernel<<<eblocks, TB>>>(probs);                   // launch 3 (profiled slot)

    for (int step = 0; step < NUM_STEPS; step++) {
        spmv_tile_kernel<<<NTILES * CTAS_PER_TILE, STEP_TPB>>>(step);
        node_kernel<<<nblocks, TB>>>(td, ew, nb, step,
                                     (step == NUM_STEPS - 1) ? 1 : 0, out);
    }
}